// round 10
// baseline (speedup 1.0000x reference)
#include <cuda_runtime.h>
#include <math.h>

// Problem constants
#define BATCH 32
#define TT 55
#define VV 32000
#define DW 256
#define DD 512
#define AA 200
#define G4 2048   // 4*D
#define NCOL (G4 + AA)   // 2248
#define WTS 2304         // padded row stride of transposed weights

#define NBLK 142   // persistent blocks
#define NTHR 256

#define MTILES 112       // padded m16-tile count (ceil(1760/16)=110, pad to 112)

// Scratch (device globals; no allocation allowed)
__device__ float    g_w4[BATCH*TT*G4];     // precomputed w4_all [b*T+t, 4D]
__device__ float    g_wr[BATCH*TT*AA];     // precomputed wr_all [b*T+t, A]
__device__ float    g_h[BATCH*DD];         // recurrent h state [B,D]
__device__ float    g_dt[BATCH*AA];        // dt state
__device__ float    g_gates[BATCH*G4];     // activated gates for current step
__device__ unsigned g_hall_tf[BATCH*TT*DD];// all h_t as tf32 bits (linear)
__device__ uint4    g_wout_p[(VV/8)*32*32];// W_out tf32, mma-fragment-permuted
__device__ uint4    g_hall_p[MTILES*64*32];// h_all tf32, mma-fragment-permuted
__device__ float    g_wt[DD*WTS];          // [Wh2h ; Wh2hr] transposed: [k][col]
__device__ float    g_wdt[AA*DD];          // Wdc transposed: [a][j]
__device__ unsigned g_arrA;                // phase1-done arrivals
__device__ unsigned g_arrB;                // phase2-done arrivals

// ---------------------------------------------------------------------------
__device__ __forceinline__ unsigned tf32r(float x) {
    unsigned y;
    asm("cvt.rna.tf32.f32 %0, %1;" : "=r"(y) : "f"(x));
    return y;
}

__global__ void init_kernel(const float* __restrict__ enc) {
    int i = blockIdx.x * blockDim.x + threadIdx.x;
    if (i < BATCH*DD) g_h[i] = enc[i];
    if (i == 0) { g_arrA = 0u; g_arrB = 0u; }
}

// ---------------------------------------------------------------------------
// W_out -> tf32 bits in mma-fragment-permuted order.
// Fragment layout (m16n8k8.row.col, B operand, thread lane l: g8=l>>2,tq=l&3):
//   b0(s) = W[n = nt*8+g8][k = s*8+tq],  b1(s) = W[nt*8+g8][s*8+tq+4]
// Packed per (nt, sp=s/2, lane): uint4 { b0(2sp), b1(2sp), b0(2sp+1), b1(2sp+1) }
// at index (nt*32 + sp)*32 + lane.
// ---------------------------------------------------------------------------
__global__ void __launch_bounds__(256) wout_permute(const float* __restrict__ W) {
    int idx = blockIdx.x * blockDim.x + threadIdx.x;   // (nt, sp, lane)
    int lane = idx & 31;
    int sp   = (idx >> 5) & 31;
    int nt   = idx >> 10;                // 0..3999
    int g8 = lane >> 2, tq = lane & 3;
    const float* row = W + (size_t)(nt*8 + g8) * DD + sp*16 + tq;
    uint4 o;
    o.x = tf32r(row[0]);
    o.y = tf32r(row[4]);
    o.z = tf32r(row[8]);
    o.w = tf32r(row[12]);
    g_wout_p[idx] = o;
}

// ---------------------------------------------------------------------------
// h_all (tf32 bits, linear [m][k]) -> fragment-permuted A.
// a0=(mt*16+g8, s*8+tq) a1=(+8 row) a2=(col+4) a3=(row+8,col+4),
// packed uint4 at (mt*64 + s)*32 + lane. Zero-fill m >= 1760 (pad tiles).
// ---------------------------------------------------------------------------
__global__ void __launch_bounds__(256) a_permute() {
    int idx = blockIdx.x * blockDim.x + threadIdx.x;   // (mt, s, lane)
    if (idx >= MTILES*64*32) return;
    int lane = idx & 31;
    int s    = (idx >> 5) & 63;
    int mt   = idx >> 11;
    int g8 = lane >> 2, tq = lane & 3;
    int m0 = mt*16 + g8, m1 = m0 + 8;
    int k0 = s*8 + tq;
    uint4 o;
    o.x = (m0 < BATCH*TT) ? g_hall_tf[(size_t)m0*DD + k0    ] : 0u;
    o.y = (m1 < BATCH*TT) ? g_hall_tf[(size_t)m1*DD + k0    ] : 0u;
    o.z = (m0 < BATCH*TT) ? g_hall_tf[(size_t)m0*DD + k0 + 4] : 0u;
    o.w = (m1 < BATCH*TT) ? g_hall_tf[(size_t)m1*DD + k0 + 4] : 0u;
    g_hall_p[idx] = o;
}

// ---- one-time weight transposes -------------------------------------------
__global__ void __launch_bounds__(256) transpose_w(
    const float* __restrict__ Wh2h, const float* __restrict__ Wh2hr)
{
    __shared__ float tile[32][33];
    const int ct = blockIdx.x;
    const int kt = blockIdx.y;
    const int tx = threadIdx.x, ty = threadIdx.y;
    #pragma unroll
    for (int i = 0; i < 4; i++) {
        int col = ct*32 + ty + i*8;
        int k   = kt*32 + tx;
        float v = 0.f;
        if (col < G4)        v = Wh2h[(size_t)col*DD + k];
        else if (col < NCOL) v = Wh2hr[(size_t)(col-G4)*DD + k];
        tile[ty + i*8][tx] = v;
    }
    __syncthreads();
    #pragma unroll
    for (int i = 0; i < 4; i++) {
        int k   = kt*32 + ty + i*8;
        int col = ct*32 + tx;
        g_wt[(size_t)k*WTS + col] = tile[tx][ty + i*8];
    }
}

__global__ void __launch_bounds__(256) transpose_wdc(const float* __restrict__ Wdc)
{
    __shared__ float tile[32][33];
    const int jt = blockIdx.x;
    const int at = blockIdx.y;
    const int tx = threadIdx.x, ty = threadIdx.y;
    #pragma unroll
    for (int i = 0; i < 4; i++) {
        int j = jt*32 + ty + i*8;
        int a = at*32 + tx;
        tile[ty + i*8][tx] = (a < AA) ? Wdc[(size_t)j*AA + a] : 0.f;
    }
    __syncthreads();
    #pragma unroll
    for (int i = 0; i < 4; i++) {
        int a = at*32 + ty + i*8;
        int j = jt*32 + tx;
        if (a < AA) g_wdt[(size_t)a*DD + j] = tile[tx][ty + i*8];
    }
}

__device__ __forceinline__ float sigmoidf_(float x) {
    return 1.f / (1.f + expf(-x));
}

// Fence-free semaphores
__device__ __forceinline__ void sem_arrive(unsigned* ctr) {
    __syncthreads();
    if (threadIdx.x == 0)
        asm volatile("red.release.gpu.global.add.u32 [%0], 1;"
                     :: "l"(ctr) : "memory");
}
__device__ __forceinline__ void sem_wait(unsigned* ctr, unsigned tgt) {
    if (threadIdx.x == 0) {
        unsigned v;
        do {
            asm volatile("ld.acquire.gpu.global.u32 %0, [%1];"
                         : "=r"(v) : "l"(ctr) : "memory");
        } while (v < tgt);
    }
    __syncthreads();
}

// ---------------------------------------------------------------------------
// Persistent recurrence kernel (unchanged from R9 — measured working).
// ---------------------------------------------------------------------------
__global__ void __launch_bounds__(NTHR, 1) recurrent_kernel(
    const float* __restrict__ bh2h, const float* __restrict__ bh2hr,
    const float* __restrict__ enc,  const float* __restrict__ act)
{
    __shared__ float smem_f[16 * DD];

    const int blk  = blockIdx.x;
    const int tid  = threadIdx.x;
    const int w    = tid >> 5;
    const int lane = tid & 31;

    const int  colg = blk >> 1;
    const int  bh   = blk & 1;
    const int  col  = colg * 32 + lane;
    const bool p1   = (col < NCOL);
    const int  b0   = bh * 16 + w * 2;
    const int  b1   = b0 + 1;

    float bias = 0.f;
    bool  is_r = false;
    int   acol = 0;
    if (p1) {
        if (col < G4) bias = bh2h[col];
        else { is_r = true; acol = col - G4; bias = bh2hr[acol]; }
    }
    float d0 = 0.f, d1 = 0.f;
    if (p1 && is_r) {
        d0 = __ldcg(act + b0 * AA + acol);
        d1 = __ldcg(act + b1 * AA + acol);
    }

    const bool p2 = (blk < 64);
    const int  colg2 = blk >> 2;
    const int  b2    = (blk & 3) * 8 + w;
    const int  j2    = colg2 * 32 + lane;
    float creg = 0.f;
    if (p2) creg = __ldcg(enc + b2 * DD + j2);

    unsigned* arrA; unsigned* arrB;
    asm("cvta.global.u64 %0, g_arrA;" : "=l"(arrA));
    asm("cvta.global.u64 %0, g_arrB;" : "=l"(arrB));

    const float* wt = g_wt + col;

    for (int t = 0; t < TT; t++) {
        sem_wait(arrB, 64u * (unsigned)t);

        {
            const float4* src = (const float4*)(g_h + bh * 16 * DD);
            #pragma unroll
            for (int i = 0; i < 8; i++) {
                int idx = i * NTHR + tid;
                float4 v = __ldcg(src + idx);
                int b  = idx >> 7;
                int kq = idx & 127;
                int base = (kq * 4) * 16 + (b >> 1) * 2 + (b & 1);
                smem_f[base     ] = v.x;
                smem_f[base + 16] = v.y;
                smem_f[base + 32] = v.z;
                smem_f[base + 48] = v.w;
            }
        }
        __syncthreads();

        if (p1) {
            const float* hw = smem_f + w * 2;
            float acc0a = 0.f, acc0b = 0.f, acc1a = 0.f, acc1b = 0.f;
            #pragma unroll 8
            for (int k = 0; k < DD; k += 2) {
                float w0 = wt[(k    ) * WTS];
                float w1 = wt[(k + 1) * WTS];
                float2 hv0 = *(const float2*)(hw + (k    ) * 16);
                float2 hv1 = *(const float2*)(hw + (k + 1) * 16);
                acc0a += w0 * hv0.x; acc1a += w0 * hv0.y;
                acc0b += w1 * hv1.x; acc1b += w1 * hv1.y;
            }
            float acc0 = acc0a + acc0b;
            float acc1 = acc1a + acc1b;
            if (!is_r) {
                float v0 = g_w4[(size_t)(b0*TT + t) * G4 + col] + acc0 + bias;
                float v1 = g_w4[(size_t)(b1*TT + t) * G4 + col] + acc1 + bias;
                v0 = (col < 3*DD) ? sigmoidf_(v0) : tanhf(v0);
                v1 = (col < 3*DD) ? sigmoidf_(v1) : tanhf(v1);
                g_gates[b0 * G4 + col] = v0;
                g_gates[b1 * G4 + col] = v1;
            } else {
                float r0 = sigmoidf_(g_wr[(size_t)(b0*TT + t) * AA + acol] + acc0 + bias);
                float r1 = sigmoidf_(g_wr[(size_t)(b1*TT + t) * AA + acol] + acc1 + bias);
                d0 *= r0;
                d1 *= r1;
                g_dt[b0 * AA + acol] = d0;
                g_dt[b1 * AA + acol] = d1;
            }
        }

        sem_arrive(arrA);

        if (p2) {
            sem_wait(arrA, 142u * (unsigned)(t + 1));

            int bb = (blk & 3) * 8;
            for (int i = tid; i < 8 * AA; i += NTHR)
                smem_f[i] = __ldcg(g_dt + bb * AA + i);
            __syncthreads();

            const float* wdt = g_wdt + j2;
            const float* dts = smem_f + w * AA;
            float acc_a = 0.f, acc_b = 0.f;
            #pragma unroll 10
            for (int a = 0; a < AA; a += 2) {
                acc_a += dts[a    ] * wdt[(a    ) * DD];
                acc_b += dts[a + 1] * wdt[(a + 1) * DD];
            }
            float dtw = tanhf(acc_a + acc_b);
            float gi = __ldcg(g_gates + b2 * G4 + j2);
            float gf = __ldcg(g_gates + b2 * G4 + DD   + j2);
            float go = __ldcg(g_gates + b2 * G4 + 2*DD + j2);
            float ch = __ldcg(g_gates + b2 * G4 + 3*DD + j2);
            creg = gf * creg + gi * ch + dtw;
            float h = go * tanhf(creg);
            g_h[b2 * DD + j2] = h;
            g_hall_tf[(size_t)(b2 * TT + t) * DD + j2] = tf32r(h);

            sem_arrive(arrB);
        }
    }
}

// ---------------------------------------------------------------------------
// fp32 tiled GEMM (two small precompute GEMMs)
// ---------------------------------------------------------------------------
#define TS 128
#define KT 8

template<bool GATHER>
__global__ void __launch_bounds__(256) gemm_tn(
    int M, int N, int K,
    const float* __restrict__ A, const int* __restrict__ idx,
    const float* __restrict__ B,
    const float* __restrict__ bias,
    float* __restrict__ C, int ldc)
{
    __shared__ float As[KT][TS];
    __shared__ float Bs[KT][TS];

    int tid = threadIdx.x;
    int lrow = tid >> 1;
    int kc   = (tid & 1) * 4;

    int gm_l = blockIdx.y * TS + lrow;
    int gn_l = blockIdx.x * TS + lrow;

    const float* aptr = nullptr;
    if (gm_l < M) {
        int ar = GATHER ? idx[gm_l] : gm_l;
        aptr = A + (size_t)ar * K;
    }
    const float* bptr = (gn_l < N) ? (B + (size_t)gn_l * K) : nullptr;

    int tx = tid & 15;
    int ty = tid >> 4;

    float acc[8][8];
    #pragma unroll
    for (int i = 0; i < 8; i++)
        #pragma unroll
        for (int j = 0; j < 8; j++) acc[i][j] = 0.f;

    for (int k0 = 0; k0 < K; k0 += KT) {
        float4 av = make_float4(0.f, 0.f, 0.f, 0.f);
        float4 bv = make_float4(0.f, 0.f, 0.f, 0.f);
        if (aptr) av = *(const float4*)(aptr + k0 + kc);
        if (bptr) bv = *(const float4*)(bptr + k0 + kc);
        __syncthreads();
        As[kc+0][lrow] = av.x; As[kc+1][lrow] = av.y;
        As[kc+2][lrow] = av.z; As[kc+3][lrow] = av.w;
        Bs[kc+0][lrow] = bv.x; Bs[kc+1][lrow] = bv.y;
        Bs[kc+2][lrow] = bv.z; Bs[kc+3][lrow] = bv.w;
        __syncthreads();
        #pragma unroll
        for (int kk = 0; kk < KT; kk++) {
            float4 a0 = *(const float4*)&As[kk][ty*8];
            float4 a1 = *(const float4*)&As[kk][ty*8+4];
            float4 b0 = *(const float4*)&Bs[kk][tx*8];
            float4 b1 = *(const float4*)&Bs[kk][tx*8+4];
            float a[8] = {a0.x,a0.y,a0.z,a0.w,a1.x,a1.y,a1.z,a1.w};
            float b[8] = {b0.x,b0.y,b0.z,b0.w,b1.x,b1.y,b1.z,b1.w};
            #pragma unroll
            for (int i = 0; i < 8; i++)
                #pragma unroll
                for (int j = 0; j < 8; j++)
                    acc[i][j] += a[i] * b[j];
        }
    }

    #pragma unroll
    for (int i = 0; i < 8; i++) {
        int gm = blockIdx.y * TS + ty*8 + i;
        if (gm < M) {
            #pragma unroll
            for (int j = 0; j < 8; j += 4) {
                int gn = blockIdx.x * TS + tx*8 + j;
                if (gn < N) {
                    float4 bs = *(const float4*)(bias + gn);
                    float4 o;
                    o.x = acc[i][j+0] + bs.x;
                    o.y = acc[i][j+1] + bs.y;
                    o.z = acc[i][j+2] + bs.z;
                    o.w = acc[i][j+3] + bs.w;
                    *(float4*)(C + (size_t)gm * ldc + gn) = o;
                }
            }
        }
    }
}

// ---------------------------------------------------------------------------
// tf32 fragment-direct GEMM v3: no smem, no barriers.
// CTA 128x256 (8 warps, warp tile 64x64: 4 m16-tiles x 8 n8-tiles).
// Operands pre-permuted in gmem to fragment order; inner loop = LDG.128 + mma.
// ---------------------------------------------------------------------------
__device__ __forceinline__ void mma_tf32(float c[4],
    unsigned a0, unsigned a1, unsigned a2, unsigned a3,
    unsigned b0, unsigned b1)
{
    asm volatile(
        "mma.sync.aligned.m16n8k8.row.col.f32.tf32.tf32.f32 "
        "{%0,%1,%2,%3}, {%4,%5,%6,%7}, {%8,%9}, {%0,%1,%2,%3};\n"
        : "+f"(c[0]), "+f"(c[1]), "+f"(c[2]), "+f"(c[3])
        : "r"(a0), "r"(a1), "r"(a2), "r"(a3), "r"(b0), "r"(b1));
}

__global__ void __launch_bounds__(256, 1) gemm_tf32_v3(
    int M,
    const float* __restrict__ bias,
    float* __restrict__ C, int ldc)
{
    const int tid  = threadIdx.x;
    const int lane = tid & 31;
    const int w    = tid >> 5;
    const int wmh  = (w & 1);            // m half (0/1)
    const int wnq  = (w >> 1);           // n quarter (0..3)
    const int g8   = lane >> 2;
    const int tq   = lane & 3;

    const int bMt = blockIdx.y * 8 + wmh * 4;    // base m16-tile (4 tiles)
    const int bNt = blockIdx.x * 32 + wnq * 8;   // base n8-tile (8 tiles)

    const uint4* aBase = g_hall_p + (size_t)bMt * 64 * 32 + lane;
    const uint4* bBase = g_wout_p + (size_t)bNt * 32 * 32 + lane;

    float acc[4][8][4];
    #pragma unroll
    for (int mi = 0; mi < 4; mi++)
        #pragma unroll
        for (int ni = 0; ni < 8; ni++)
            #pragma unroll
            for (int q = 0; q < 4; q++) acc[mi][ni][q] = 0.f;

    #pragma unroll 1
    for (int kt = 0; kt < 16; kt++) {
        // B fragments for this k-tile: 8 n-tiles x 2 sp
        uint4 bf[8][2];
        #pragma unroll
        for (int ni = 0; ni < 8; ni++) {
            bf[ni][0] = __ldg(bBase + ((size_t)ni * 32 + kt*2    ) * 32);
            bf[ni][1] = __ldg(bBase + ((size_t)ni * 32 + kt*2 + 1) * 32);
        }
        #pragma unroll
        for (int s4 = 0; s4 < 4; s4++) {
            const int s = kt*4 + s4;
            uint4 af[4];
            #pragma unroll
            for (int mi = 0; mi < 4; mi++)
                af[mi] = __ldg(aBase + ((size_t)mi * 64 + s) * 32);
            #pragma unroll
            for (int mi = 0; mi < 4; mi++)
                #pragma unroll
                for (int ni = 0; ni < 8; ni++) {
                    unsigned b0 = (s4 & 1) ? bf[ni][s4>>1].z : bf[ni][s4>>1].x;
                    unsigned b1 = (s4 & 1) ? bf[ni][s4>>1].w : bf[ni][s4>>1].y;
                    mma_tf32(acc[mi][ni], af[mi].x, af[mi].y, af[mi].z, af[mi].w,
                             b0, b1);
                }
        }
    }

    // epilogue
    #pragma unroll
    for (int mi = 0; mi < 4; mi++) {
        int gm0 = blockIdx.y * 128 + wmh * 64 + mi*16 + g8;
        int gm1 = gm0 + 8;
        #pragma unroll
        for (int ni = 0; ni < 8; ni++) {
            int gn = blockIdx.x * 256 + wnq * 64 + ni*8 + tq*2;
            float2 bs = *(const float2*)(bias + gn);
            if (gm0 < M) {
                float2 o0; o0.x = acc[mi][ni][0] + bs.x; o0.y = acc[mi][ni][1] + bs.y;
                *(float2*)(C + (size_t)gm0 * ldc + gn) = o0;
            }
            if (gm1 < M) {
                float2 o1; o1.x = acc[mi][ni][2] + bs.x; o1.y = acc[mi][ni][3] + bs.y;
                *(float2*)(C + (size_t)gm1 * ldc + gn) = o1;
            }
        }
    }
}

// ---------------------------------------------------------------------------
// Launch
// ---------------------------------------------------------------------------
extern "C" void kernel_launch(void* const* d_in, const int* in_sizes, int n_in,
                              void* d_out, int out_size) {
    const int*   tgt   = (const int*)  d_in[0];
    const float* enc   = (const float*)d_in[1];
    const float* act   = (const float*)d_in[2];
    const float* E     = (const float*)d_in[3];
    const float* Ww2h  = (const float*)d_in[4];
    const float* bw2h  = (const float*)d_in[5];
    const float* Wh2h  = (const float*)d_in[6];
    const float* bh2h  = (const float*)d_in[7];
    const float* Ww2hr = (const float*)d_in[8];
    const float* bw2hr = (const float*)d_in[9];
    const float* Wh2hr = (const float*)d_in[10];
    const float* bh2hr = (const float*)d_in[11];
    const float* Wdc   = (const float*)d_in[12];
    const float* Wout  = (const float*)d_in[13];
    const float* bout  = (const float*)d_in[14];
    float* out = (float*)d_out;

    float *pw4, *pwr;
    cudaGetSymbolAddress((void**)&pw4, g_w4);
    cudaGetSymbolAddress((void**)&pwr, g_wr);

    // state init (h = enc, semaphores = 0)
    init_kernel<<<(BATCH*DD + 255) / 256, 256>>>(enc);

    // one-time weight transforms
    transpose_w<<<dim3(71, 16), dim3(32, 8)>>>(Wh2h, Wh2hr);
    transpose_wdc<<<dim3(16, 7), dim3(32, 8)>>>(Wdc);
    wout_permute<<<(VV/8)*32*32 / 256, 256>>>(Wout);

    // precompute w4_all and wr_all
    {
        dim3 g1((G4 + TS - 1) / TS, (BATCH*TT + TS - 1) / TS);
        gemm_tn<true><<<g1, 256>>>(BATCH*TT, G4, DW, E, tgt, Ww2h, bw2h, pw4, G4);
        dim3 g2((AA + TS - 1) / TS, (BATCH*TT + TS - 1) / TS);
        gemm_tn<true><<<g2, 256>>>(BATCH*TT, AA, DW, E, tgt, Ww2hr, bw2hr, pwr, AA);
    }

    // whole recurrence in ONE persistent kernel
    recurrent_kernel<<<NBLK, NTHR>>>(bh2h, bh2hr, enc, act);

    // permute h_all into fragment order
    a_permute<<<(MTILES*64*32 + 255) / 256, 256>>>();

    // dominant output projection: fragment-direct tensor-core GEMM
    {
        dim3 g3(VV / 256, (BATCH*TT + 127) / 128);   // 125 x 14
        gemm_tf32_v3<<<g3, 256>>>(BATCH*TT, bout, out, VV);
    }
}

// round 11
// speedup vs baseline: 1.4994x; 1.4994x over previous
#include <cuda_runtime.h>
#include <math.h>

// Problem constants
#define BATCH 32
#define TT 55
#define VV 32000
#define DW 256
#define DD 512
#define AA 200
#define G4 2048   // 4*D
#define NCOL (G4 + AA)   // 2248
#define WTS 2304         // padded row stride of transposed weights

#define NBLK 142   // persistent blocks
#define NTHR 256

#define MTILES 112       // padded m16-tile count

// Scratch (device globals; no allocation allowed)
__device__ float    g_w4[BATCH*TT*G4];
__device__ float    g_wr[BATCH*TT*AA];
__device__ float    g_h[BATCH*DD];
__device__ float    g_dt[BATCH*AA];
__device__ float    g_gates[BATCH*G4];
__device__ unsigned g_hall_tf[BATCH*TT*DD];
__device__ uint4    g_wout_p[(VV/8)*32*32];
__device__ uint4    g_hall_p[MTILES*64*32];
__device__ float    g_wt[DD*WTS];          // [Wh2h ; Wh2hr] transposed: [k][col]
__device__ float    g_wdt[AA*DD];          // Wdc transposed: [a][j]
__device__ unsigned g_arrA;
__device__ unsigned g_arrB;

// ---------------------------------------------------------------------------
__device__ __forceinline__ unsigned tf32r(float x) {
    unsigned y;
    asm("cvt.rna.tf32.f32 %0, %1;" : "=r"(y) : "f"(x));
    return y;
}

__global__ void init_kernel(const float* __restrict__ enc) {
    int i = blockIdx.x * blockDim.x + threadIdx.x;
    if (i < BATCH*DD) g_h[i] = enc[i];
    if (i == 0) { g_arrA = 0u; g_arrB = 0u; }
}

__global__ void __launch_bounds__(256) wout_permute(const float* __restrict__ W) {
    int idx = blockIdx.x * blockDim.x + threadIdx.x;
    int lane = idx & 31;
    int sp   = (idx >> 5) & 31;
    int nt   = idx >> 10;
    int g8 = lane >> 2, tq = lane & 3;
    const float* row = W + (size_t)(nt*8 + g8) * DD + sp*16 + tq;
    uint4 o;
    o.x = tf32r(row[0]);
    o.y = tf32r(row[4]);
    o.z = tf32r(row[8]);
    o.w = tf32r(row[12]);
    g_wout_p[idx] = o;
}

__global__ void __launch_bounds__(256) a_permute() {
    int idx = blockIdx.x * blockDim.x + threadIdx.x;
    if (idx >= MTILES*64*32) return;
    int lane = idx & 31;
    int s    = (idx >> 5) & 63;
    int mt   = idx >> 11;
    int g8 = lane >> 2, tq = lane & 3;
    int m0 = mt*16 + g8, m1 = m0 + 8;
    int k0 = s*8 + tq;
    uint4 o;
    o.x = (m0 < BATCH*TT) ? g_hall_tf[(size_t)m0*DD + k0    ] : 0u;
    o.y = (m1 < BATCH*TT) ? g_hall_tf[(size_t)m1*DD + k0    ] : 0u;
    o.z = (m0 < BATCH*TT) ? g_hall_tf[(size_t)m0*DD + k0 + 4] : 0u;
    o.w = (m1 < BATCH*TT) ? g_hall_tf[(size_t)m1*DD + k0 + 4] : 0u;
    g_hall_p[idx] = o;
}

// ---- one-time weight transposes -------------------------------------------
__global__ void __launch_bounds__(256) transpose_w(
    const float* __restrict__ Wh2h, const float* __restrict__ Wh2hr)
{
    __shared__ float tile[32][33];
    const int ct = blockIdx.x;
    const int kt = blockIdx.y;
    const int tx = threadIdx.x, ty = threadIdx.y;
    #pragma unroll
    for (int i = 0; i < 4; i++) {
        int col = ct*32 + ty + i*8;
        int k   = kt*32 + tx;
        float v = 0.f;
        if (col < G4)        v = Wh2h[(size_t)col*DD + k];
        else if (col < NCOL) v = Wh2hr[(size_t)(col-G4)*DD + k];
        tile[ty + i*8][tx] = v;
    }
    __syncthreads();
    #pragma unroll
    for (int i = 0; i < 4; i++) {
        int k   = kt*32 + ty + i*8;
        int col = ct*32 + tx;
        g_wt[(size_t)k*WTS + col] = tile[tx][ty + i*8];
    }
}

__global__ void __launch_bounds__(256) transpose_wdc(const float* __restrict__ Wdc)
{
    __shared__ float tile[32][33];
    const int jt = blockIdx.x;
    const int at = blockIdx.y;
    const int tx = threadIdx.x, ty = threadIdx.y;
    #pragma unroll
    for (int i = 0; i < 4; i++) {
        int j = jt*32 + ty + i*8;
        int a = at*32 + tx;
        tile[ty + i*8][tx] = (a < AA) ? Wdc[(size_t)j*AA + a] : 0.f;
    }
    __syncthreads();
    #pragma unroll
    for (int i = 0; i < 4; i++) {
        int a = at*32 + ty + i*8;
        int j = jt*32 + tx;
        if (a < AA) g_wdt[(size_t)a*DD + j] = tile[tx][ty + i*8];
    }
}

__device__ __forceinline__ float sigmoidf_(float x) {
    return 1.f / (1.f + expf(-x));
}

// Fence-free semaphores
__device__ __forceinline__ void sem_arrive(unsigned* ctr) {
    __syncthreads();
    if (threadIdx.x == 0)
        asm volatile("red.release.gpu.global.add.u32 [%0], 1;"
                     :: "l"(ctr) : "memory");
}
__device__ __forceinline__ void sem_wait(unsigned* ctr, unsigned tgt) {
    if (threadIdx.x == 0) {
        unsigned v;
        do {
            asm volatile("ld.acquire.gpu.global.u32 %0, [%1];"
                         : "=r"(v) : "l"(ctr) : "memory");
        } while (v < tgt);
    }
    __syncthreads();
}

// ---------------------------------------------------------------------------
// Persistent recurrence kernel v3:
//  - weights REGISTER-RESIDENT: warp w owns k in [64w, 64w+64); each thread
//    caches its column's 64 weights in regs (loaded once). Zero per-step
//    weight memory traffic.
//  - h staged row-major [b][k] (phase1 reads are warp-uniform broadcasts),
//    conflict-free LDG.128 -> STS.128 copy.
//  - per-(col,batch) totals reduced from 8 warp-partials in smem; activation
//    + dt update done by fixed owner threads (dt in registers).
// dynamic smem: hbuf 16*512 floats (32KB) + part 8*512 floats (16KB) = 48KB
// ---------------------------------------------------------------------------
__global__ void __launch_bounds__(NTHR, 1) recurrent_kernel(
    const float* __restrict__ bh2h, const float* __restrict__ bh2hr,
    const float* __restrict__ enc,  const float* __restrict__ act)
{
    extern __shared__ float smem[];
    float* hbuf = smem;           // 8192 floats: h rows [b][k]
    float* part = smem + 8192;    // 4096 floats: warp partials / dt stage

    const int blk  = blockIdx.x;
    const int tid  = threadIdx.x;
    const int w    = tid >> 5;
    const int lane = tid & 31;

    const int colg  = blk >> 1;
    const int bh    = blk & 1;
    const int col   = colg * 32 + lane;   // this thread's column (phase1 MACs)
    const int kbase = w * 64;             // this warp's k-slice

    // ---- load this thread's 64 weights into registers (once) ----
    float wreg[64];
    #pragma unroll
    for (int i = 0; i < 64; i++)
        wreg[i] = g_wt[(size_t)(kbase + i) * WTS + col];

    // ---- reduction-ownership setup: thread owns p0=tid, p1=tid+256 ----
    // p -> (b = p>>5, c = p&31); col_g = colg*32+c; batch = bh*16+b
    float biasv[2];
    float dreg[2];
    #pragma unroll
    for (int pi = 0; pi < 2; pi++) {
        int p  = tid + pi * 256;
        int b  = p >> 5;
        int cg = colg * 32 + (p & 31);
        int batch = bh * 16 + b;
        biasv[pi] = 0.f; dreg[pi] = 0.f;
        if (cg < G4) biasv[pi] = bh2h[cg];
        else if (cg < NCOL) {
            biasv[pi] = bh2hr[cg - G4];
            dreg[pi]  = __ldcg(act + batch * AA + (cg - G4));
        }
    }

    // ---- phase2 setup (blocks 0..63) ----
    const bool p2 = (blk < 64);
    const int  colg2 = blk >> 2;
    const int  b2    = (blk & 3) * 8 + w;
    const int  j2    = colg2 * 32 + lane;
    float creg = 0.f;
    if (p2) creg = __ldcg(enc + b2 * DD + j2);

    unsigned* arrA; unsigned* arrB;
    asm("cvta.global.u64 %0, g_arrA;" : "=l"(arrA));
    asm("cvta.global.u64 %0, g_arrB;" : "=l"(arrB));

    for (int t = 0; t < TT; t++) {
        // ---- wait until h(t) is ready ----
        sem_wait(arrB, 64u * (unsigned)t);

        // ---- stage h rows [bh*16 .. +16) linearly (conflict-free) ----
        {
            const float4* src = (const float4*)(g_h + bh * 16 * DD);
            float4* dst = (float4*)hbuf;
            #pragma unroll
            for (int i = 0; i < 8; i++)
                dst[i * NTHR + tid] = __ldcg(src + i * NTHR + tid);
        }
        __syncthreads();

        // ---- phase1: partial dots over this warp's k-slice ----
        {
            float acc[16];
            #pragma unroll
            for (int b = 0; b < 16; b++) acc[b] = 0.f;
            const float* hw = hbuf + kbase;
            #pragma unroll
            for (int k4 = 0; k4 < 64; k4 += 4) {
                float w0 = wreg[k4], w1 = wreg[k4+1];
                float w2 = wreg[k4+2], w3 = wreg[k4+3];
                #pragma unroll
                for (int b = 0; b < 16; b++) {
                    float4 hv = *(const float4*)(hw + b * DD + k4);
                    acc[b] += w0*hv.x + w1*hv.y + w2*hv.z + w3*hv.w;
                }
            }
            #pragma unroll
            for (int b = 0; b < 16; b++)
                part[w * 512 + b * 32 + lane] = acc[b];
        }
        __syncthreads();

        // ---- reduce partials, activate, store gates / update dt ----
        #pragma unroll
        for (int pi = 0; pi < 2; pi++) {
            int p  = tid + pi * 256;
            float s = part[p]          + part[p + 512]
                    + part[p + 1024]   + part[p + 1536]
                    + part[p + 2048]   + part[p + 2560]
                    + part[p + 3072]   + part[p + 3584];
            int b  = p >> 5;
            int cg = colg * 32 + (p & 31);
            int batch = bh * 16 + b;
            if (cg < G4) {
                float v = g_w4[(size_t)(batch*TT + t) * G4 + cg] + s + biasv[pi];
                v = (cg < 3*DD) ? sigmoidf_(v) : tanhf(v);
                g_gates[batch * G4 + cg] = v;
            } else if (cg < NCOL) {
                int acol = cg - G4;
                float r = sigmoidf_(g_wr[(size_t)(batch*TT + t) * AA + acol]
                                    + s + biasv[pi]);
                dreg[pi] *= r;
                g_dt[batch * AA + acol] = dreg[pi];
            }
        }

        // ---- announce phase1 done ----
        sem_arrive(arrA);

        // ---- phase2 on blocks 0..63 ----
        if (p2) {
            sem_wait(arrA, 142u * (unsigned)(t + 1));

            int bb = (blk & 3) * 8;
            for (int i = tid; i < 8 * AA; i += NTHR)
                part[i] = __ldcg(g_dt + bb * AA + i);
            __syncthreads();

            const float* wdt = g_wdt + j2;
            const float* dts = part + w * AA;
            float acc_a = 0.f, acc_b = 0.f;
            #pragma unroll 10
            for (int a = 0; a < AA; a += 2) {
                acc_a += dts[a    ] * wdt[(a    ) * DD];
                acc_b += dts[a + 1] * wdt[(a + 1) * DD];
            }
            float dtw = tanhf(acc_a + acc_b);
            float gi = __ldcg(g_gates + b2 * G4 + j2);
            float gf = __ldcg(g_gates + b2 * G4 + DD   + j2);
            float go = __ldcg(g_gates + b2 * G4 + 2*DD + j2);
            float ch = __ldcg(g_gates + b2 * G4 + 3*DD + j2);
            creg = gf * creg + gi * ch + dtw;
            float h = go * tanhf(creg);
            g_h[b2 * DD + j2] = h;
            g_hall_tf[(size_t)(b2 * TT + t) * DD + j2] = tf32r(h);

            sem_arrive(arrB);
        }
    }
}

// ---------------------------------------------------------------------------
// fp32 tiled GEMM (two small precompute GEMMs)
// ---------------------------------------------------------------------------
#define TS 128
#define KT 8

template<bool GATHER>
__global__ void __launch_bounds__(256) gemm_tn(
    int M, int N, int K,
    const float* __restrict__ A, const int* __restrict__ idx,
    const float* __restrict__ B,
    const float* __restrict__ bias,
    float* __restrict__ C, int ldc)
{
    __shared__ float As[KT][TS];
    __shared__ float Bs[KT][TS];

    int tid = threadIdx.x;
    int lrow = tid >> 1;
    int kc   = (tid & 1) * 4;

    int gm_l = blockIdx.y * TS + lrow;
    int gn_l = blockIdx.x * TS + lrow;

    const float* aptr = nullptr;
    if (gm_l < M) {
        int ar = GATHER ? idx[gm_l] : gm_l;
        aptr = A + (size_t)ar * K;
    }
    const float* bptr = (gn_l < N) ? (B + (size_t)gn_l * K) : nullptr;

    int tx = tid & 15;
    int ty = tid >> 4;

    float acc[8][8];
    #pragma unroll
    for (int i = 0; i < 8; i++)
        #pragma unroll
        for (int j = 0; j < 8; j++) acc[i][j] = 0.f;

    for (int k0 = 0; k0 < K; k0 += KT) {
        float4 av = make_float4(0.f, 0.f, 0.f, 0.f);
        float4 bv = make_float4(0.f, 0.f, 0.f, 0.f);
        if (aptr) av = *(const float4*)(aptr + k0 + kc);
        if (bptr) bv = *(const float4*)(bptr + k0 + kc);
        __syncthreads();
        As[kc+0][lrow] = av.x; As[kc+1][lrow] = av.y;
        As[kc+2][lrow] = av.z; As[kc+3][lrow] = av.w;
        Bs[kc+0][lrow] = bv.x; Bs[kc+1][lrow] = bv.y;
        Bs[kc+2][lrow] = bv.z; Bs[kc+3][lrow] = bv.w;
        __syncthreads();
        #pragma unroll
        for (int kk = 0; kk < KT; kk++) {
            float4 a0 = *(const float4*)&As[kk][ty*8];
            float4 a1 = *(const float4*)&As[kk][ty*8+4];
            float4 b0 = *(const float4*)&Bs[kk][tx*8];
            float4 b1 = *(const float4*)&Bs[kk][tx*8+4];
            float a[8] = {a0.x,a0.y,a0.z,a0.w,a1.x,a1.y,a1.z,a1.w};
            float b[8] = {b0.x,b0.y,b0.z,b0.w,b1.x,b1.y,b1.z,b1.w};
            #pragma unroll
            for (int i = 0; i < 8; i++)
                #pragma unroll
                for (int j = 0; j < 8; j++)
                    acc[i][j] += a[i] * b[j];
        }
    }

    #pragma unroll
    for (int i = 0; i < 8; i++) {
        int gm = blockIdx.y * TS + ty*8 + i;
        if (gm < M) {
            #pragma unroll
            for (int j = 0; j < 8; j += 4) {
                int gn = blockIdx.x * TS + tx*8 + j;
                if (gn < N) {
                    float4 bs = *(const float4*)(bias + gn);
                    float4 o;
                    o.x = acc[i][j+0] + bs.x;
                    o.y = acc[i][j+1] + bs.y;
                    o.z = acc[i][j+2] + bs.z;
                    o.w = acc[i][j+3] + bs.w;
                    *(float4*)(C + (size_t)gm * ldc + gn) = o;
                }
            }
        }
    }
}

// ---------------------------------------------------------------------------
// tf32 fragment-direct GEMM v3 (neutral vs v2; kept — simpler)
// ---------------------------------------------------------------------------
__device__ __forceinline__ void mma_tf32(float c[4],
    unsigned a0, unsigned a1, unsigned a2, unsigned a3,
    unsigned b0, unsigned b1)
{
    asm volatile(
        "mma.sync.aligned.m16n8k8.row.col.f32.tf32.tf32.f32 "
        "{%0,%1,%2,%3}, {%4,%5,%6,%7}, {%8,%9}, {%0,%1,%2,%3};\n"
        : "+f"(c[0]), "+f"(c[1]), "+f"(c[2]), "+f"(c[3])
        : "r"(a0), "r"(a1), "r"(a2), "r"(a3), "r"(b0), "r"(b1));
}

__global__ void __launch_bounds__(256, 1) gemm_tf32_v3(
    int M,
    const float* __restrict__ bias,
    float* __restrict__ C, int ldc)
{
    const int tid  = threadIdx.x;
    const int lane = tid & 31;
    const int w    = tid >> 5;
    const int wmh  = (w & 1);
    const int wnq  = (w >> 1);
    const int g8   = lane >> 2;
    const int tq   = lane & 3;

    const int bMt = blockIdx.y * 8 + wmh * 4;
    const int bNt = blockIdx.x * 32 + wnq * 8;

    const uint4* aBase = g_hall_p + (size_t)bMt * 64 * 32 + lane;
    const uint4* bBase = g_wout_p + (size_t)bNt * 32 * 32 + lane;

    float acc[4][8][4];
    #pragma unroll
    for (int mi = 0; mi < 4; mi++)
        #pragma unroll
        for (int ni = 0; ni < 8; ni++)
            #pragma unroll
            for (int q = 0; q < 4; q++) acc[mi][ni][q] = 0.f;

    #pragma unroll 1
    for (int kt = 0; kt < 16; kt++) {
        uint4 bf[8][2];
        #pragma unroll
        for (int ni = 0; ni < 8; ni++) {
            bf[ni][0] = __ldg(bBase + ((size_t)ni * 32 + kt*2    ) * 32);
            bf[ni][1] = __ldg(bBase + ((size_t)ni * 32 + kt*2 + 1) * 32);
        }
        #pragma unroll
        for (int s4 = 0; s4 < 4; s4++) {
            const int s = kt*4 + s4;
            uint4 af[4];
            #pragma unroll
            for (int mi = 0; mi < 4; mi++)
                af[mi] = __ldg(aBase + ((size_t)mi * 64 + s) * 32);
            #pragma unroll
            for (int mi = 0; mi < 4; mi++)
                #pragma unroll
                for (int ni = 0; ni < 8; ni++) {
                    unsigned b0 = (s4 & 1) ? bf[ni][s4>>1].z : bf[ni][s4>>1].x;
                    unsigned b1 = (s4 & 1) ? bf[ni][s4>>1].w : bf[ni][s4>>1].y;
                    mma_tf32(acc[mi][ni], af[mi].x, af[mi].y, af[mi].z, af[mi].w,
                             b0, b1);
                }
        }
    }

    #pragma unroll
    for (int mi = 0; mi < 4; mi++) {
        int gm0 = blockIdx.y * 128 + wmh * 64 + mi*16 + g8;
        int gm1 = gm0 + 8;
        #pragma unroll
        for (int ni = 0; ni < 8; ni++) {
            int gn = blockIdx.x * 256 + wnq * 64 + ni*8 + tq*2;
            float2 bs = *(const float2*)(bias + gn);
            if (gm0 < M) {
                float2 o0; o0.x = acc[mi][ni][0] + bs.x; o0.y = acc[mi][ni][1] + bs.y;
                *(float2*)(C + (size_t)gm0 * ldc + gn) = o0;
            }
            if (gm1 < M) {
                float2 o1; o1.x = acc[mi][ni][2] + bs.x; o1.y = acc[mi][ni][3] + bs.y;
                *(float2*)(C + (size_t)gm1 * ldc + gn) = o1;
            }
        }
    }
}

// ---------------------------------------------------------------------------
// Launch  (order chosen so recurrent_kernel is the 6th launch -> ncu -s 5)
// ---------------------------------------------------------------------------
extern "C" void kernel_launch(void* const* d_in, const int* in_sizes, int n_in,
                              void* d_out, int out_size) {
    const int*   tgt   = (const int*)  d_in[0];
    const float* enc   = (const float*)d_in[1];
    const float* act   = (const float*)d_in[2];
    const float* E     = (const float*)d_in[3];
    const float* Ww2h  = (const float*)d_in[4];
    const float* bw2h  = (const float*)d_in[5];
    const float* Wh2h  = (const float*)d_in[6];
    const float* bh2h  = (const float*)d_in[7];
    const float* Ww2hr = (const float*)d_in[8];
    const float* bw2hr = (const float*)d_in[9];
    const float* Wh2hr = (const float*)d_in[10];
    const float* bh2hr = (const float*)d_in[11];
    const float* Wdc   = (const float*)d_in[12];
    const float* Wout  = (const float*)d_in[13];
    const float* bout  = (const float*)d_in[14];
    float* out = (float*)d_out;

    float *pw4, *pwr;
    cudaGetSymbolAddress((void**)&pw4, g_w4);
    cudaGetSymbolAddress((void**)&pwr, g_wr);

    // 1: state init (h = enc, semaphores = 0)
    init_kernel<<<(BATCH*DD + 255) / 256, 256>>>(enc);

    // 2,3: one-time weight transposes (needed by recurrence)
    transpose_w<<<dim3(71, 16), dim3(32, 8)>>>(Wh2h, Wh2hr);
    transpose_wdc<<<dim3(16, 7), dim3(32, 8)>>>(Wdc);

    // 4,5: precompute w4_all and wr_all
    {
        dim3 g1((G4 + TS - 1) / TS, (BATCH*TT + TS - 1) / TS);
        gemm_tn<true><<<g1, 256>>>(BATCH*TT, G4, DW, E, tgt, Ww2h, bw2h, pw4, G4);
        dim3 g2((AA + TS - 1) / TS, (BATCH*TT + TS - 1) / TS);
        gemm_tn<true><<<g2, 256>>>(BATCH*TT, AA, DW, E, tgt, Ww2hr, bw2hr, pwr, AA);
    }

    // 6: whole recurrence in ONE persistent kernel  (ncu -s 5 profiles this)
    recurrent_kernel<<<NBLK, NTHR, 48*1024>>>(bh2h, bh2hr, enc, act);

    // 7: W_out permute (only needed before gemm_v3)
    wout_permute<<<(VV/8)*32*32 / 256, 256>>>(Wout);

    // 8: permute h_all into fragment order
    a_permute<<<(MTILES*64*32 + 255) / 256, 256>>>();

    // 9: dominant output projection
    {
        dim3 g3(VV / 256, (BATCH*TT + 127) / 128);
        gemm_tf32_v3<<<g3, 256>>>(BATCH*TT, bout, out, VV);
    }
}